// round 2
// baseline (speedup 1.0000x reference)
#include <cuda_runtime.h>
#include <math.h>

#define T_STEPS 250
#define NN      256
#define IN_DIM  1024
#define HH      1024
#define OUT_DIM 35
#define BR      4
#define INB     256

// Persistent recurrent state (device globals: no allocation allowed)
__device__ float g_state[NN * BR * HH];   // 4 MB
__device__ float g_v1[NN * HH];           // 1 MB
__device__ float g_s1[NN * HH];           // 1 MB
__device__ float g_alpha[BR * HH];
__device__ float g_v2[NN * OUT_DIM];
__device__ float g_acc[NN * OUT_DIM];

__device__ __forceinline__ float2 ull2f2(unsigned long long v) {
    float2 r;
    asm("mov.b64 {%0, %1}, %2;" : "=f"(r.x), "=f"(r.y) : "l"(v));
    return r;
}

__global__ void init_kernel(const float* __restrict__ taus) {
    int idx = blockIdx.x * blockDim.x + threadIdx.x;   // 4096*256 = 1048576
    g_state[idx] = 0.f;
    if (idx < NN * HH) g_v1[idx] = 0.f;
    if (idx < BR * HH) g_alpha[idx] = 1.f / (1.f + expf(-taus[idx]));
    if (idx < NN * OUT_DIM) { g_v2[idx] = 0.f; g_acc[idx] = 0.f; }
}

// ---------------------------------------------------------------------------
// Kernel A: per-branch GEMM + dendritic state update + LIF1 -> s1
// Tile: BM=32 (n) x BH=64 (h), BK=32, 256 threads, grid (16, 8)
// ---------------------------------------------------------------------------
#define BM 32
#define BH 64
#define BK 32

__global__ __launch_bounds__(256) void stepA_kernel(
    const float* __restrict__ xt,      // [NN, IN_DIM] slice for this t
    const float* __restrict__ Wb,      // [BR, INB, HH]
    const float* __restrict__ bbias,   // [BR, HH]
    const float* __restrict__ tau1p)   // [1]
{
    __shared__ float Xs[BK][BM + 2];   // pad to keep float2 loads 8B-aligned, spread banks
    __shared__ float Ws[BK][BH];

    const int tid = threadIdx.x;
    const int tx = tid & 15;           // h dir: 16 threads * 4 h
    const int ty = tid >> 4;           // n dir: 16 threads * 2 n
    const int h0 = blockIdx.x * BH;
    const int n0 = blockIdx.y * BM;
    const float tau1v = *tau1p;

    // loader indices
    const int lxr = tid >> 3;          // 0..31 : n row
    const int lxc = (tid & 7) * 4;     // 0..28 : k col (float4)
    const int lwr = tid >> 4;          // 0..15 : k row
    const int lwc = (tid & 15) * 4;    // 0..60 : h col (float4)

    float comb[2][4];
#pragma unroll
    for (int i = 0; i < 2; ++i)
#pragma unroll
        for (int j = 0; j < 4; ++j) comb[i][j] = 0.f;

    for (int b = 0; b < BR; ++b) {
        unsigned long long accp[2][2];
        accp[0][0] = accp[0][1] = accp[1][0] = accp[1][1] = 0ULL;  // {0.f,0.f}

        const float* xb = xt + b * INB;
        const float* wb = Wb + b * INB * HH;

        for (int k0 = 0; k0 < INB; k0 += BK) {
            float4 xv = *reinterpret_cast<const float4*>(&xb[(n0 + lxr) * IN_DIM + k0 + lxc]);
            float4 wv0 = *reinterpret_cast<const float4*>(&wb[(k0 + lwr) * HH + h0 + lwc]);
            float4 wv1 = *reinterpret_cast<const float4*>(&wb[(k0 + lwr + 16) * HH + h0 + lwc]);
            __syncthreads();   // protect previous iteration's smem reads
            Xs[lxc + 0][lxr] = xv.x;
            Xs[lxc + 1][lxr] = xv.y;
            Xs[lxc + 2][lxr] = xv.z;
            Xs[lxc + 3][lxr] = xv.w;
            *reinterpret_cast<float4*>(&Ws[lwr][lwc]) = wv0;
            *reinterpret_cast<float4*>(&Ws[lwr + 16][lwc]) = wv1;
            __syncthreads();
#pragma unroll
            for (int k = 0; k < BK; ++k) {
                float2 a = *reinterpret_cast<const float2*>(&Xs[k][ty * 2]);
                const unsigned long long* bp =
                    reinterpret_cast<const unsigned long long*>(&Ws[k][tx * 4]);
                unsigned long long b0 = bp[0], b1 = bp[1];
                unsigned long long a0, a1;
                asm("mov.b64 %0, {%1, %1};" : "=l"(a0) : "f"(a.x));
                asm("mov.b64 %0, {%1, %1};" : "=l"(a1) : "f"(a.y));
                asm("fma.rn.f32x2 %0, %1, %2, %0;" : "+l"(accp[0][0]) : "l"(a0), "l"(b0));
                asm("fma.rn.f32x2 %0, %1, %2, %0;" : "+l"(accp[0][1]) : "l"(a0), "l"(b1));
                asm("fma.rn.f32x2 %0, %1, %2, %0;" : "+l"(accp[1][0]) : "l"(a1), "l"(b0));
                asm("fma.rn.f32x2 %0, %1, %2, %0;" : "+l"(accp[1][1]) : "l"(a1), "l"(b1));
            }
        }

        // branch epilogue: leaky dendritic integration + accumulate into comb
#pragma unroll
        for (int i = 0; i < 2; ++i) {
            const int n = n0 + ty * 2 + i;
            const int h = h0 + tx * 4;
            float2 lo = ull2f2(accp[i][0]);
            float2 hi = ull2f2(accp[i][1]);
            float bi[4] = {lo.x, lo.y, hi.x, hi.y};

            const int sidx = (n * BR + b) * HH + h;
            float4 st = *reinterpret_cast<float4*>(&g_state[sidx]);
            float4 al = *reinterpret_cast<const float4*>(&g_alpha[b * HH + h]);
            float4 bv = *reinterpret_cast<const float4*>(&bbias[b * HH + h]);

            float in0 = bi[0] + bv.x, in1 = bi[1] + bv.y;
            float in2 = bi[2] + bv.z, in3 = bi[3] + bv.w;
            st.x = al.x * st.x + (1.f - al.x) * in0;
            st.y = al.y * st.y + (1.f - al.y) * in1;
            st.z = al.z * st.z + (1.f - al.z) * in2;
            st.w = al.w * st.w + (1.f - al.w) * in3;
            *reinterpret_cast<float4*>(&g_state[sidx]) = st;
            comb[i][0] += st.x; comb[i][1] += st.y;
            comb[i][2] += st.z; comb[i][3] += st.w;
        }
    }

    // LIF1: charge (decay_input), fire, hard reset
#pragma unroll
    for (int i = 0; i < 2; ++i) {
        const int n = n0 + ty * 2 + i;
        const int h = h0 + tx * 4;
        const int vidx = n * HH + h;
        float4 v = *reinterpret_cast<float4*>(&g_v1[vidx]);
        v.x = v.x + (comb[i][0] - v.x) / tau1v;
        v.y = v.y + (comb[i][1] - v.y) / tau1v;
        v.z = v.z + (comb[i][2] - v.z) / tau1v;
        v.w = v.w + (comb[i][3] - v.w) / tau1v;
        float4 s;
        s.x = (v.x >= 1.f) ? 1.f : 0.f;
        s.y = (v.y >= 1.f) ? 1.f : 0.f;
        s.z = (v.z >= 1.f) ? 1.f : 0.f;
        s.w = (v.w >= 1.f) ? 1.f : 0.f;
        v.x *= (1.f - s.x); v.y *= (1.f - s.y);
        v.z *= (1.f - s.z); v.w *= (1.f - s.w);
        *reinterpret_cast<float4*>(&g_v1[vidx]) = v;
        *reinterpret_cast<float4*>(&g_s1[vidx]) = s;
    }
}

// ---------------------------------------------------------------------------
// Kernel B: h2 = s1 @ W2 + b2, LIF2, spike accumulation. One block per n.
// ---------------------------------------------------------------------------
__global__ __launch_bounds__(128) void stepB_kernel(
    const float* __restrict__ W2,     // [HH, OUT_DIM]
    const float* __restrict__ b2,     // [OUT_DIM]
    const float* __restrict__ tau2p)  // [1]
{
    __shared__ float red[128][OUT_DIM + 1];
    const int n = blockIdx.x;
    const int tid = threadIdx.x;

    float acc[OUT_DIM];
#pragma unroll
    for (int o = 0; o < OUT_DIM; ++o) acc[o] = 0.f;

    for (int h = tid; h < HH; h += 128) {
        float sv = g_s1[n * HH + h];
        if (sv != 0.f) {
            const float* w = W2 + h * OUT_DIM;
#pragma unroll
            for (int o = 0; o < OUT_DIM; ++o) acc[o] += w[o];
        }
    }
#pragma unroll
    for (int o = 0; o < OUT_DIM; ++o) red[tid][o] = acc[o];
    __syncthreads();

    if (tid < OUT_DIM) {
        float sum = b2[tid];
#pragma unroll 8
        for (int j = 0; j < 128; ++j) sum += red[j][tid];
        const int idx = n * OUT_DIM + tid;
        float v = g_v2[idx];
        v = v + (sum - v) / (*tau2p);
        float s = (v >= 1.f) ? 1.f : 0.f;
        g_v2[idx] = v * (1.f - s);
        g_acc[idx] += s;
    }
}

// ---------------------------------------------------------------------------
// Final: log_softmax over OUT for each n
// ---------------------------------------------------------------------------
__global__ void final_kernel(float* __restrict__ out) {
    const int n = threadIdx.x;   // 256 threads, 1 block
    float f[OUT_DIM];
    float m = -1e30f;
#pragma unroll
    for (int o = 0; o < OUT_DIM; ++o) {
        f[o] = g_acc[n * OUT_DIM + o];
        m = fmaxf(m, f[o]);
    }
    float s = 0.f;
#pragma unroll
    for (int o = 0; o < OUT_DIM; ++o) s += expf(f[o] - m);
    float l = logf(s);
#pragma unroll
    for (int o = 0; o < OUT_DIM; ++o) out[n * OUT_DIM + o] = f[o] - m - l;
}

extern "C" void kernel_launch(void* const* d_in, const int* in_sizes, int n_in,
                              void* d_out, int out_size) {
    const float* x    = (const float*)d_in[0];   // [T, N, IN]
    const float* Wb   = (const float*)d_in[1];   // [B, INB, H]
    const float* bb   = (const float*)d_in[2];   // [B, H]
    const float* taus = (const float*)d_in[3];   // [B, H]
    const float* W2   = (const float*)d_in[4];   // [H, OUT]
    const float* b2   = (const float*)d_in[5];   // [OUT]
    const float* tau1 = (const float*)d_in[6];   // [1]
    const float* tau2 = (const float*)d_in[7];   // [1]
    float* out = (float*)d_out;                  // [N, OUT]

    init_kernel<<<4096, 256>>>(taus);

    dim3 gridA(HH / BH, NN / BM);   // (16, 8)
    for (int t = 0; t < T_STEPS; ++t) {
        const float* xt = x + (size_t)t * NN * IN_DIM;
        stepA_kernel<<<gridA, 256>>>(xt, Wb, bb, tau1);
        stepB_kernel<<<NN, 128>>>(W2, b2, tau2);
    }
    final_kernel<<<1, 256>>>(out);
}

// round 4
// speedup vs baseline: 3.5585x; 3.5585x over previous
#include <cuda_runtime.h>
#include <math.h>

#define T_STEPS 250
#define NN      256
#define IN_DIM  1024
#define HH      1024
#define OUT_DIM 35
#define BR      4
#define INB     256
#define TC      25                 // timesteps per chunk
#define NCHUNK  (T_STEPS / TC)     // 10
#define MC      (TC * NN)          // 6400 rows per chunk

// Persistent state (device globals: no allocation allowed)
__device__ float g_state[NN * BR * HH];     // 4 MB
__device__ float g_v1[NN * HH];             // 1 MB
__device__ float g_alpha[BR * HH];
__device__ float g_v2[NN * OUT_DIM];
__device__ float g_acc[NN * OUT_DIM];
__device__ float g_Y[(size_t)MC * BR * HH]; // 104.9 MB chunk buffer of branch_in

__global__ void init_kernel(const float* __restrict__ taus) {
    int idx = blockIdx.x * blockDim.x + threadIdx.x;   // 1048576 threads
    g_state[idx] = 0.f;
    if (idx < NN * HH) g_v1[idx] = 0.f;
    if (idx < BR * HH) g_alpha[idx] = 1.f / (1.f + expf(-taus[idx]));
    if (idx < NN * OUT_DIM) { g_v2[idx] = 0.f; g_acc[idx] = 0.f; }
}

// ---------------------------------------------------------------------------
// Batched branch GEMM: for branch br, Y[r, br, h] = sum_k Xc[r, br*256+k]*Wb[br,k,h] + bb[br,h]
// 128x128 tile, BK=16, 256 threads, 8x8 per thread, f32x2 packed FMA.
// ---------------------------------------------------------------------------
__global__ __launch_bounds__(256, 2) void gemm_kernel(
    const float* __restrict__ Xc,   // [MC, IN_DIM] chunk base
    const float* __restrict__ Wb,   // [BR, INB, HH]
    const float* __restrict__ bb)   // [BR, HH]
{
    __shared__ float As[2][16][128];
    __shared__ float Bs[2][16][128];

    const int tid  = threadIdx.x;
    const int h0v  = blockIdx.x * 128;
    const int m0   = blockIdx.y * 128;
    const int br   = blockIdx.z;

    // loaders
    const int ar = tid >> 1, ak = (tid & 1) * 8;         // A: 128 rows x 16 k
    const int bk = tid >> 4, bh = (tid & 15) * 8;        // B: 16 k x 128 h
    const float* aptr = Xc + (size_t)(m0 + ar) * IN_DIM + br * INB + ak;
    const float* bptr = Wb + ((size_t)br * INB + bk) * HH + h0v + bh;

    // compute mapping: 8 warps as 4x2, lanes 4x8
    const int wid = tid >> 5, lane = tid & 31;
    const int trow = (wid >> 1) * 32 + (lane >> 3) * 8;
    const int tcol = (wid & 1) * 64 + (lane & 7) * 8;

    unsigned long long acc[8][4];
#pragma unroll
    for (int i = 0; i < 8; ++i)
#pragma unroll
        for (int j = 0; j < 4; ++j) acc[i][j] = 0ULL;

    // prologue: load k-tile 0 into buffer 0
    {
        float4 a0 = *(const float4*)(aptr);
        float4 a1 = *(const float4*)(aptr + 4);
        float4 b0 = *(const float4*)(bptr);
        float4 b1 = *(const float4*)(bptr + 4);
        As[0][ak + 0][ar] = a0.x; As[0][ak + 1][ar] = a0.y;
        As[0][ak + 2][ar] = a0.z; As[0][ak + 3][ar] = a0.w;
        As[0][ak + 4][ar] = a1.x; As[0][ak + 5][ar] = a1.y;
        As[0][ak + 6][ar] = a1.z; As[0][ak + 7][ar] = a1.w;
        *(float4*)&Bs[0][bk][bh]     = b0;
        *(float4*)&Bs[0][bk][bh + 4] = b1;
    }
    __syncthreads();

    int buf = 0;
#pragma unroll 1
    for (int k0 = 0; k0 < INB; k0 += 16) {
        const bool more = (k0 + 16) < INB;
        float4 na0, na1, nb0, nb1;
        if (more) {
            na0 = *(const float4*)(aptr + k0 + 16);
            na1 = *(const float4*)(aptr + k0 + 20);
            nb0 = *(const float4*)(bptr + (size_t)(k0 + 16) * HH);
            nb1 = *(const float4*)(bptr + (size_t)(k0 + 16) * HH + 4);
        }
#pragma unroll
        for (int k = 0; k < 16; ++k) {
            float4 af0 = *(const float4*)&As[buf][k][trow];
            float4 af1 = *(const float4*)&As[buf][k][trow + 4];
            const unsigned long long* bp =
                (const unsigned long long*)&Bs[buf][k][tcol];
            unsigned long long bq0 = bp[0], bq1 = bp[1], bq2 = bp[2], bq3 = bp[3];
            float av[8] = {af0.x, af0.y, af0.z, af0.w, af1.x, af1.y, af1.z, af1.w};
#pragma unroll
            for (int i = 0; i < 8; ++i) {
                unsigned long long ad;
                asm("mov.b64 %0, {%1, %1};" : "=l"(ad) : "f"(av[i]));
                asm("fma.rn.f32x2 %0, %1, %2, %0;" : "+l"(acc[i][0]) : "l"(ad), "l"(bq0));
                asm("fma.rn.f32x2 %0, %1, %2, %0;" : "+l"(acc[i][1]) : "l"(ad), "l"(bq1));
                asm("fma.rn.f32x2 %0, %1, %2, %0;" : "+l"(acc[i][2]) : "l"(ad), "l"(bq2));
                asm("fma.rn.f32x2 %0, %1, %2, %0;" : "+l"(acc[i][3]) : "l"(ad), "l"(bq3));
            }
        }
        if (more) {
            const int nb = buf ^ 1;
            As[nb][ak + 0][ar] = na0.x; As[nb][ak + 1][ar] = na0.y;
            As[nb][ak + 2][ar] = na0.z; As[nb][ak + 3][ar] = na0.w;
            As[nb][ak + 4][ar] = na1.x; As[nb][ak + 5][ar] = na1.y;
            As[nb][ak + 6][ar] = na1.z; As[nb][ak + 7][ar] = na1.w;
            *(float4*)&Bs[nb][bk][bh]     = nb0;
            *(float4*)&Bs[nb][bk][bh + 4] = nb1;
            __syncthreads();
            buf = nb;
        }
    }

    // epilogue: add bias, store to g_Y[r][br][h]
    float4 bias0 = *(const float4*)(bb + br * HH + h0v + tcol);
    float4 bias1 = *(const float4*)(bb + br * HH + h0v + tcol + 4);
#pragma unroll
    for (int i = 0; i < 8; ++i) {
        float o[8];
#pragma unroll
        for (int j = 0; j < 4; ++j) {
            float lo, hi;
            asm("mov.b64 {%0, %1}, %2;" : "=f"(lo), "=f"(hi) : "l"(acc[i][j]));
            o[2 * j] = lo; o[2 * j + 1] = hi;
        }
        o[0] += bias0.x; o[1] += bias0.y; o[2] += bias0.z; o[3] += bias0.w;
        o[4] += bias1.x; o[5] += bias1.y; o[6] += bias1.z; o[7] += bias1.w;
        size_t r = (size_t)(m0 + trow + i);
        float* yp = &g_Y[(r * BR + br) * HH + h0v + tcol];
        float4 w0 = {o[0], o[1], o[2], o[3]};
        float4 w1 = {o[4], o[5], o[6], o[7]};
        *(float4*)yp       = w0;
        *(float4*)(yp + 4) = w1;
    }
}

// ---------------------------------------------------------------------------
// Fused recurrence over one chunk: dendritic state + LIF1 + spike-gated
// output GEMM + LIF2 + accumulation. 128 blocks x 512 threads; block owns 2 n.
// ---------------------------------------------------------------------------
#define W2_STRIDE 36
#define SM_W2   (HH * W2_STRIDE)            // 36864 floats
#define SM_RED  (2 * 256 * W2_STRIDE)       // 18432 floats
#define SM_REDP (2 * 4 * W2_STRIDE)         // 288 floats
#define SMEM_RECUR_BYTES ((SM_W2 + SM_RED + SM_REDP) * 4)

__global__ __launch_bounds__(512, 1) void recur_kernel(
    const float* __restrict__ W2,      // [HH, OUT_DIM]
    const float* __restrict__ b2,      // [OUT_DIM]
    const float* __restrict__ tau1p,
    const float* __restrict__ tau2p)
{
    extern __shared__ float sm[];
    float* W2s  = sm;
    float* red  = sm + SM_W2;
    float* redp = red + SM_RED;

    const int tid = threadIdx.x;
    const int n_l = tid >> 8;           // 0,1
    const int hq  = tid & 255;
    const int n   = blockIdx.x * 2 + n_l;
    const int h0  = hq * 4;

    // stage W2 into smem (padded stride 36, pad col = 0)
    for (int i = tid; i < SM_W2; i += 512) {
        int h = i / W2_STRIDE, o = i - h * W2_STRIDE;
        W2s[i] = (o < OUT_DIM) ? W2[h * OUT_DIM + o] : 0.f;
    }

    // resident state
    float4 st[BR], al[BR];
#pragma unroll
    for (int b = 0; b < BR; ++b) {
        st[b] = *(float4*)&g_state[((size_t)n * BR + b) * HH + h0];
        al[b] = *(const float4*)&g_alpha[b * HH + h0];
    }
    float4 v1 = *(float4*)&g_v1[(size_t)n * HH + h0];
    const float tau1v = *tau1p, tau2v = *tau2p;

    // reduction-owner threads keep v2/acc
    const bool own = (tid < 72);
    const int o_o = tid % 36, n_o = tid / 36;
    float v2 = 0.f, accv = 0.f, b2v = 0.f;
    int vidx = 0;
    if (own && o_o < OUT_DIM) {
        vidx = (blockIdx.x * 2 + n_o) * OUT_DIM + o_o;
        v2 = g_v2[vidx]; accv = g_acc[vidx]; b2v = b2[o_o];
    }
    __syncthreads();

#pragma unroll 1
    for (int t = 0; t < TC; ++t) {
        // dendritic integration + combine
        float4 cb = {0.f, 0.f, 0.f, 0.f};
#pragma unroll
        for (int b = 0; b < BR; ++b) {
            float4 y = *(const float4*)&g_Y[(((size_t)t * NN + n) * BR + b) * HH + h0];
            st[b].x = al[b].x * st[b].x + (1.f - al[b].x) * y.x;
            st[b].y = al[b].y * st[b].y + (1.f - al[b].y) * y.y;
            st[b].z = al[b].z * st[b].z + (1.f - al[b].z) * y.z;
            st[b].w = al[b].w * st[b].w + (1.f - al[b].w) * y.w;
            cb.x += st[b].x; cb.y += st[b].y; cb.z += st[b].z; cb.w += st[b].w;
        }
        // LIF1
        v1.x = v1.x + (cb.x - v1.x) / tau1v;
        v1.y = v1.y + (cb.y - v1.y) / tau1v;
        v1.z = v1.z + (cb.z - v1.z) / tau1v;
        v1.w = v1.w + (cb.w - v1.w) / tau1v;
        float s0 = (v1.x >= 1.f) ? 1.f : 0.f;
        float s1 = (v1.y >= 1.f) ? 1.f : 0.f;
        float s2 = (v1.z >= 1.f) ? 1.f : 0.f;
        float s3 = (v1.w >= 1.f) ? 1.f : 0.f;
        v1.x *= (1.f - s0); v1.y *= (1.f - s1);
        v1.z *= (1.f - s2); v1.w *= (1.f - s3);

        // spike-gated accumulation of W2 rows
        float4 a4[9];
#pragma unroll
        for (int q = 0; q < 9; ++q) a4[q] = make_float4(0.f, 0.f, 0.f, 0.f);
        if (s0 != 0.f) {
            const float4* w = (const float4*)&W2s[(h0 + 0) * W2_STRIDE];
#pragma unroll
            for (int q = 0; q < 9; ++q) { float4 v = w[q];
                a4[q].x += v.x; a4[q].y += v.y; a4[q].z += v.z; a4[q].w += v.w; }
        }
        if (s1 != 0.f) {
            const float4* w = (const float4*)&W2s[(h0 + 1) * W2_STRIDE];
#pragma unroll
            for (int q = 0; q < 9; ++q) { float4 v = w[q];
                a4[q].x += v.x; a4[q].y += v.y; a4[q].z += v.z; a4[q].w += v.w; }
        }
        if (s2 != 0.f) {
            const float4* w = (const float4*)&W2s[(h0 + 2) * W2_STRIDE];
#pragma unroll
            for (int q = 0; q < 9; ++q) { float4 v = w[q];
                a4[q].x += v.x; a4[q].y += v.y; a4[q].z += v.z; a4[q].w += v.w; }
        }
        if (s3 != 0.f) {
            const float4* w = (const float4*)&W2s[(h0 + 3) * W2_STRIDE];
#pragma unroll
            for (int q = 0; q < 9; ++q) { float4 v = w[q];
                a4[q].x += v.x; a4[q].y += v.y; a4[q].z += v.z; a4[q].w += v.w; }
        }
        float* rp = &red[((size_t)n_l * 256 + hq) * W2_STRIDE];
#pragma unroll
        for (int q = 0; q < 9; ++q) *(float4*)(rp + q * 4) = a4[q];
        __syncthreads();

        // stage1: 288 threads, each sums 64 partials
        if (tid < 288) {
            int nl = tid / 144, r = tid % 144;
            int o = r % 36, seg = r / 36;
            const float* c = &red[((size_t)nl * 256 + seg * 64) * W2_STRIDE + o];
            float s = 0.f;
#pragma unroll 8
            for (int j = 0; j < 64; ++j) s += c[(size_t)j * W2_STRIDE];
            redp[(nl * 4 + seg) * W2_STRIDE + o] = s;
        }
        __syncthreads();

        // stage2: LIF2 + accumulate (owner threads)
        if (own && o_o < OUT_DIM) {
            float h2 = redp[(n_o * 4 + 0) * W2_STRIDE + o_o]
                     + redp[(n_o * 4 + 1) * W2_STRIDE + o_o]
                     + redp[(n_o * 4 + 2) * W2_STRIDE + o_o]
                     + redp[(n_o * 4 + 3) * W2_STRIDE + o_o] + b2v;
            v2 = v2 + (h2 - v2) / tau2v;
            float s = (v2 >= 1.f) ? 1.f : 0.f;
            v2 *= (1.f - s);
            accv += s;
        }
        __syncthreads();   // protect red/redp for next iteration
    }

    // persist state
#pragma unroll
    for (int b = 0; b < BR; ++b)
        *(float4*)&g_state[((size_t)n * BR + b) * HH + h0] = st[b];
    *(float4*)&g_v1[(size_t)n * HH + h0] = v1;
    if (own && o_o < OUT_DIM) { g_v2[vidx] = v2; g_acc[vidx] = accv; }
}

// ---------------------------------------------------------------------------
// Final log_softmax
// ---------------------------------------------------------------------------
__global__ void final_kernel(float* __restrict__ out) {
    const int n = threadIdx.x;   // 256 threads, 1 block
    float f[OUT_DIM];
    float m = -1e30f;
#pragma unroll
    for (int o = 0; o < OUT_DIM; ++o) {
        f[o] = g_acc[n * OUT_DIM + o];
        m = fmaxf(m, f[o]);
    }
    float s = 0.f;
#pragma unroll
    for (int o = 0; o < OUT_DIM; ++o) s += expf(f[o] - m);
    float l = logf(s);
#pragma unroll
    for (int o = 0; o < OUT_DIM; ++o) out[n * OUT_DIM + o] = f[o] - m - l;
}

extern "C" void kernel_launch(void* const* d_in, const int* in_sizes, int n_in,
                              void* d_out, int out_size) {
    const float* x    = (const float*)d_in[0];   // [T, N, IN]
    const float* Wb   = (const float*)d_in[1];   // [B, INB, H]
    const float* bb   = (const float*)d_in[2];   // [B, H]
    const float* taus = (const float*)d_in[3];   // [B, H]
    const float* W2   = (const float*)d_in[4];   // [H, OUT]
    const float* b2   = (const float*)d_in[5];   // [OUT]
    const float* tau1 = (const float*)d_in[6];   // [1]
    const float* tau2 = (const float*)d_in[7];   // [1]
    float* out = (float*)d_out;                  // [N, OUT]

    static bool attr_set = false;
    if (!attr_set) {
        cudaFuncSetAttribute(recur_kernel,
                             cudaFuncAttributeMaxDynamicSharedMemorySize,
                             SMEM_RECUR_BYTES);
        attr_set = true;
    }

    init_kernel<<<4096, 256>>>(taus);

    dim3 ggrid(HH / 128, MC / 128, BR);   // (8, 50, 4)
    for (int c = 0; c < NCHUNK; ++c) {
        const float* Xc = x + (size_t)c * MC * IN_DIM;
        gemm_kernel<<<ggrid, 256>>>(Xc, Wb, bb);
        recur_kernel<<<128, 512, SMEM_RECUR_BYTES>>>(W2, b2, tau1, tau2);
    }
    final_kernel<<<1, 256>>>(out);
}

// round 5
// speedup vs baseline: 3.6732x; 1.0322x over previous
#include <cuda_runtime.h>
#include <math.h>

#define T_STEPS 250
#define NN      256
#define IN_DIM  1024
#define HH      1024
#define OUT_DIM 35
#define BR      4
#define INB     256
#define TC      25                 // timesteps per chunk
#define NCHUNK  (T_STEPS / TC)     // 10
#define MC      (TC * NN)          // 6400 rows per chunk

// Persistent state (device globals: no allocation allowed)
__device__ float g_state[NN * BR * HH];     // 4 MB
__device__ float g_v1[NN * HH];             // 1 MB
__device__ float g_alpha[BR * HH];
__device__ float g_v2[NN * OUT_DIM];
__device__ float g_acc[NN * OUT_DIM];
__device__ float g_Y[(size_t)MC * BR * HH]; // 104.9 MB chunk buffer of branch_in

__global__ void init_kernel(const float* __restrict__ taus) {
    int idx = blockIdx.x * blockDim.x + threadIdx.x;   // 1048576 threads
    g_state[idx] = 0.f;
    if (idx < NN * HH) g_v1[idx] = 0.f;
    if (idx < BR * HH) g_alpha[idx] = 1.f / (1.f + expf(-taus[idx]));
    if (idx < NN * OUT_DIM) { g_v2[idx] = 0.f; g_acc[idx] = 0.f; }
}

// ---------------------------------------------------------------------------
// Batched branch GEMM: Y[r, br, h] = sum_k Xc[r, br*256+k]*Wb[br,k,h] + bb[br,h]
// Block tile 256(M) x 128(H), BK=16, 256 threads, 16x8 per thread.
// A consumed as packed f32x2 M-pairs (no dup MOVs); B duplicated (8 MOVs/k).
// ---------------------------------------------------------------------------
__global__ __launch_bounds__(256, 1) void gemm_kernel(
    const float* __restrict__ Xc,   // [MC, IN_DIM] chunk base
    const float* __restrict__ Wb,   // [BR, INB, HH]
    const float* __restrict__ bb)   // [BR, HH]
{
    __shared__ float As[2][16][256];   // [buf][k][m]  (m contiguous)
    __shared__ float Bs[2][16][128];   // [buf][k][h]

    const int tid  = threadIdx.x;
    const int h0v  = blockIdx.x * 128;
    const int m0   = blockIdx.y * 256;
    const int br   = blockIdx.z;

    // compute mapping: 16 m-groups x 16 h-groups
    const int tx = tid & 15;               // h group
    const int ty = tid >> 4;               // m group
    const int mB = ty * 16;                // m offset within block tile
    const int hB = tx * 8;                 // h offset within block tile

    // loaders
    // A: thread tid loads row m=tid, 16 k (4x LDG.128), scatter-stores 16 STS.32
    const float* aptr = Xc + (size_t)(m0 + tid) * IN_DIM + br * INB;
    // B: 16 k x 128 h; thread: k=tid>>4, h=(tid&15)*8 (2x LDG.128 / STS.128)
    const int bk = tid >> 4, bh = (tid & 15) * 8;
    const float* bptr = Wb + ((size_t)br * INB + bk) * HH + h0v + bh;

    unsigned long long acc[8][8];          // [m-pair][h]
#pragma unroll
    for (int i = 0; i < 8; ++i)
#pragma unroll
        for (int j = 0; j < 8; ++j) acc[i][j] = 0ULL;

    // prologue: k-tile 0 -> buffer 0
    {
        float4 a0 = *(const float4*)(aptr + 0);
        float4 a1 = *(const float4*)(aptr + 4);
        float4 a2 = *(const float4*)(aptr + 8);
        float4 a3 = *(const float4*)(aptr + 12);
        float4 b0 = *(const float4*)(bptr);
        float4 b1 = *(const float4*)(bptr + 4);
        As[0][ 0][tid] = a0.x; As[0][ 1][tid] = a0.y;
        As[0][ 2][tid] = a0.z; As[0][ 3][tid] = a0.w;
        As[0][ 4][tid] = a1.x; As[0][ 5][tid] = a1.y;
        As[0][ 6][tid] = a1.z; As[0][ 7][tid] = a1.w;
        As[0][ 8][tid] = a2.x; As[0][ 9][tid] = a2.y;
        As[0][10][tid] = a2.z; As[0][11][tid] = a2.w;
        As[0][12][tid] = a3.x; As[0][13][tid] = a3.y;
        As[0][14][tid] = a3.z; As[0][15][tid] = a3.w;
        *(float4*)&Bs[0][bk][bh]     = b0;
        *(float4*)&Bs[0][bk][bh + 4] = b1;
    }
    __syncthreads();

    int buf = 0;
#pragma unroll 1
    for (int k0 = 0; k0 < INB; k0 += 16) {
        const bool more = (k0 + 16) < INB;
        float4 na0, na1, na2, na3, nb0, nb1;
        if (more) {
            na0 = *(const float4*)(aptr + k0 + 16);
            na1 = *(const float4*)(aptr + k0 + 20);
            na2 = *(const float4*)(aptr + k0 + 24);
            na3 = *(const float4*)(aptr + k0 + 28);
            nb0 = *(const float4*)(bptr + (size_t)(k0 + 16) * HH);
            nb1 = *(const float4*)(bptr + (size_t)(k0 + 16) * HH + 4);
        }
#pragma unroll
        for (int k = 0; k < 16; ++k) {
            // A: 16 m as 8 packed f32x2 (direct LDS.128, no dup)
            ulonglong2 aq0 = *(const ulonglong2*)&As[buf][k][mB + 0];
            ulonglong2 aq1 = *(const ulonglong2*)&As[buf][k][mB + 4];
            ulonglong2 aq2 = *(const ulonglong2*)&As[buf][k][mB + 8];
            ulonglong2 aq3 = *(const ulonglong2*)&As[buf][k][mB + 12];
            unsigned long long a2p[8] = {aq0.x, aq0.y, aq1.x, aq1.y,
                                         aq2.x, aq2.y, aq3.x, aq3.y};
            // B: 8 h scalars, duplicated into both lanes
            float4 bf0 = *(const float4*)&Bs[buf][k][hB];
            float4 bf1 = *(const float4*)&Bs[buf][k][hB + 4];
            float bv[8] = {bf0.x, bf0.y, bf0.z, bf0.w,
                           bf1.x, bf1.y, bf1.z, bf1.w};
            unsigned long long bd[8];
#pragma unroll
            for (int j = 0; j < 8; ++j)
                asm("mov.b64 %0, {%1, %1};" : "=l"(bd[j]) : "f"(bv[j]));
#pragma unroll
            for (int i = 0; i < 8; ++i)
#pragma unroll
                for (int j = 0; j < 8; ++j)
                    asm("fma.rn.f32x2 %0, %1, %2, %0;"
                        : "+l"(acc[i][j]) : "l"(a2p[i]), "l"(bd[j]));
        }
        if (more) {
            const int nb = buf ^ 1;
            As[nb][ 0][tid] = na0.x; As[nb][ 1][tid] = na0.y;
            As[nb][ 2][tid] = na0.z; As[nb][ 3][tid] = na0.w;
            As[nb][ 4][tid] = na1.x; As[nb][ 5][tid] = na1.y;
            As[nb][ 6][tid] = na1.z; As[nb][ 7][tid] = na1.w;
            As[nb][ 8][tid] = na2.x; As[nb][ 9][tid] = na2.y;
            As[nb][10][tid] = na2.z; As[nb][11][tid] = na2.w;
            As[nb][12][tid] = na3.x; As[nb][13][tid] = na3.y;
            As[nb][14][tid] = na3.z; As[nb][15][tid] = na3.w;
            *(float4*)&Bs[nb][bk][bh]     = nb0;
            *(float4*)&Bs[nb][bk][bh + 4] = nb1;
            __syncthreads();
            buf = nb;
        }
    }

    // epilogue: unpack, add bias, store 16 rows x 8 h
    float4 bias0 = *(const float4*)(bb + br * HH + h0v + hB);
    float4 bias1 = *(const float4*)(bb + br * HH + h0v + hB + 4);
    const float bvv[8] = {bias0.x, bias0.y, bias0.z, bias0.w,
                          bias1.x, bias1.y, bias1.z, bias1.w};
#pragma unroll
    for (int i = 0; i < 8; ++i) {
        float lo[8], hi[8];
#pragma unroll
        for (int j = 0; j < 8; ++j)
            asm("mov.b64 {%0, %1}, %2;" : "=f"(lo[j]), "=f"(hi[j]) : "l"(acc[i][j]));
        size_t r0 = (size_t)(m0 + mB + 2 * i);
        float* yp0 = &g_Y[(r0 * BR + br) * HH + h0v + hB];
        float* yp1 = yp0 + (size_t)BR * HH;
        float4 w;
        w.x = lo[0] + bvv[0]; w.y = lo[1] + bvv[1];
        w.z = lo[2] + bvv[2]; w.w = lo[3] + bvv[3];
        *(float4*)yp0 = w;
        w.x = lo[4] + bvv[4]; w.y = lo[5] + bvv[5];
        w.z = lo[6] + bvv[6]; w.w = lo[7] + bvv[7];
        *(float4*)(yp0 + 4) = w;
        w.x = hi[0] + bvv[0]; w.y = hi[1] + bvv[1];
        w.z = hi[2] + bvv[2]; w.w = hi[3] + bvv[3];
        *(float4*)yp1 = w;
        w.x = hi[4] + bvv[4]; w.y = hi[5] + bvv[5];
        w.z = hi[6] + bvv[6]; w.w = hi[7] + bvv[7];
        *(float4*)(yp1 + 4) = w;
    }
}

// ---------------------------------------------------------------------------
// Fused recurrence over one chunk (unchanged from R4)
// ---------------------------------------------------------------------------
#define W2_STRIDE 36
#define SM_W2   (HH * W2_STRIDE)
#define SM_RED  (2 * 256 * W2_STRIDE)
#define SM_REDP (2 * 4 * W2_STRIDE)
#define SMEM_RECUR_BYTES ((SM_W2 + SM_RED + SM_REDP) * 4)

__global__ __launch_bounds__(512, 1) void recur_kernel(
    const float* __restrict__ W2,
    const float* __restrict__ b2,
    const float* __restrict__ tau1p,
    const float* __restrict__ tau2p)
{
    extern __shared__ float sm[];
    float* W2s  = sm;
    float* red  = sm + SM_W2;
    float* redp = red + SM_RED;

    const int tid = threadIdx.x;
    const int n_l = tid >> 8;
    const int hq  = tid & 255;
    const int n   = blockIdx.x * 2 + n_l;
    const int h0  = hq * 4;

    for (int i = tid; i < SM_W2; i += 512) {
        int h = i / W2_STRIDE, o = i - h * W2_STRIDE;
        W2s[i] = (o < OUT_DIM) ? W2[h * OUT_DIM + o] : 0.f;
    }

    float4 st[BR], al[BR];
#pragma unroll
    for (int b = 0; b < BR; ++b) {
        st[b] = *(float4*)&g_state[((size_t)n * BR + b) * HH + h0];
        al[b] = *(const float4*)&g_alpha[b * HH + h0];
    }
    float4 v1 = *(float4*)&g_v1[(size_t)n * HH + h0];
    const float tau1v = *tau1p, tau2v = *tau2p;

    const bool own = (tid < 72);
    const int o_o = tid % 36, n_o = tid / 36;
    float v2 = 0.f, accv = 0.f, b2v = 0.f;
    int vidx = 0;
    if (own && o_o < OUT_DIM) {
        vidx = (blockIdx.x * 2 + n_o) * OUT_DIM + o_o;
        v2 = g_v2[vidx]; accv = g_acc[vidx]; b2v = b2[o_o];
    }
    __syncthreads();

#pragma unroll 1
    for (int t = 0; t < TC; ++t) {
        float4 cb = {0.f, 0.f, 0.f, 0.f};
#pragma unroll
        for (int b = 0; b < BR; ++b) {
            float4 y = *(const float4*)&g_Y[(((size_t)t * NN + n) * BR + b) * HH + h0];
            st[b].x = al[b].x * st[b].x + (1.f - al[b].x) * y.x;
            st[b].y = al[b].y * st[b].y + (1.f - al[b].y) * y.y;
            st[b].z = al[b].z * st[b].z + (1.f - al[b].z) * y.z;
            st[b].w = al[b].w * st[b].w + (1.f - al[b].w) * y.w;
            cb.x += st[b].x; cb.y += st[b].y; cb.z += st[b].z; cb.w += st[b].w;
        }
        v1.x = v1.x + (cb.x - v1.x) / tau1v;
        v1.y = v1.y + (cb.y - v1.y) / tau1v;
        v1.z = v1.z + (cb.z - v1.z) / tau1v;
        v1.w = v1.w + (cb.w - v1.w) / tau1v;
        float s0 = (v1.x >= 1.f) ? 1.f : 0.f;
        float s1 = (v1.y >= 1.f) ? 1.f : 0.f;
        float s2 = (v1.z >= 1.f) ? 1.f : 0.f;
        float s3 = (v1.w >= 1.f) ? 1.f : 0.f;
        v1.x *= (1.f - s0); v1.y *= (1.f - s1);
        v1.z *= (1.f - s2); v1.w *= (1.f - s3);

        float4 a4[9];
#pragma unroll
        for (int q = 0; q < 9; ++q) a4[q] = make_float4(0.f, 0.f, 0.f, 0.f);
        if (s0 != 0.f) {
            const float4* w = (const float4*)&W2s[(h0 + 0) * W2_STRIDE];
#pragma unroll
            for (int q = 0; q < 9; ++q) { float4 v = w[q];
                a4[q].x += v.x; a4[q].y += v.y; a4[q].z += v.z; a4[q].w += v.w; }
        }
        if (s1 != 0.f) {
            const float4* w = (const float4*)&W2s[(h0 + 1) * W2_STRIDE];
#pragma unroll
            for (int q = 0; q < 9; ++q) { float4 v = w[q];
                a4[q].x += v.x; a4[q].y += v.y; a4[q].z += v.z; a4[q].w += v.w; }
        }
        if (s2 != 0.f) {
            const float4* w = (const float4*)&W2s[(h0 + 2) * W2_STRIDE];
#pragma unroll
            for (int q = 0; q < 9; ++q) { float4 v = w[q];
                a4[q].x += v.x; a4[q].y += v.y; a4[q].z += v.z; a4[q].w += v.w; }
        }
        if (s3 != 0.f) {
            const float4* w = (const float4*)&W2s[(h0 + 3) * W2_STRIDE];
#pragma unroll
            for (int q = 0; q < 9; ++q) { float4 v = w[q];
                a4[q].x += v.x; a4[q].y += v.y; a4[q].z += v.z; a4[q].w += v.w; }
        }
        float* rp = &red[((size_t)n_l * 256 + hq) * W2_STRIDE];
#pragma unroll
        for (int q = 0; q < 9; ++q) *(float4*)(rp + q * 4) = a4[q];
        __syncthreads();

        if (tid < 288) {
            int nl = tid / 144, r = tid % 144;
            int o = r % 36, seg = r / 36;
            const float* c = &red[((size_t)nl * 256 + seg * 64) * W2_STRIDE + o];
            float s = 0.f;
#pragma unroll 8
            for (int j = 0; j < 64; ++j) s += c[(size_t)j * W2_STRIDE];
            redp[(nl * 4 + seg) * W2_STRIDE + o] = s;
        }
        __syncthreads();

        if (own && o_o < OUT_DIM) {
            float h2 = redp[(n_o * 4 + 0) * W2_STRIDE + o_o]
                     + redp[(n_o * 4 + 1) * W2_STRIDE + o_o]
                     + redp[(n_o * 4 + 2) * W2_STRIDE + o_o]
                     + redp[(n_o * 4 + 3) * W2_STRIDE + o_o] + b2v;
            v2 = v2 + (h2 - v2) / tau2v;
            float s = (v2 >= 1.f) ? 1.f : 0.f;
            v2 *= (1.f - s);
            accv += s;
        }
        __syncthreads();
    }

#pragma unroll
    for (int b = 0; b < BR; ++b)
        *(float4*)&g_state[((size_t)n * BR + b) * HH + h0] = st[b];
    *(float4*)&g_v1[(size_t)n * HH + h0] = v1;
    if (own && o_o < OUT_DIM) { g_v2[vidx] = v2; g_acc[vidx] = accv; }
}

// ---------------------------------------------------------------------------
// Final log_softmax
// ---------------------------------------------------------------------------
__global__ void final_kernel(float* __restrict__ out) {
    const int n = threadIdx.x;
    float f[OUT_DIM];
    float m = -1e30f;
#pragma unroll
    for (int o = 0; o < OUT_DIM; ++o) {
        f[o] = g_acc[n * OUT_DIM + o];
        m = fmaxf(m, f[o]);
    }
    float s = 0.f;
#pragma unroll
    for (int o = 0; o < OUT_DIM; ++o) s += expf(f[o] - m);
    float l = logf(s);
#pragma unroll
    for (int o = 0; o < OUT_DIM; ++o) out[n * OUT_DIM + o] = f[o] - m - l;
}

extern "C" void kernel_launch(void* const* d_in, const int* in_sizes, int n_in,
                              void* d_out, int out_size) {
    const float* x    = (const float*)d_in[0];
    const float* Wb   = (const float*)d_in[1];
    const float* bb   = (const float*)d_in[2];
    const float* taus = (const float*)d_in[3];
    const float* W2   = (const float*)d_in[4];
    const float* b2   = (const float*)d_in[5];
    const float* tau1 = (const float*)d_in[6];
    const float* tau2 = (const float*)d_in[7];
    float* out = (float*)d_out;

    static bool attr_set = false;
    if (!attr_set) {
        cudaFuncSetAttribute(recur_kernel,
                             cudaFuncAttributeMaxDynamicSharedMemorySize,
                             SMEM_RECUR_BYTES);
        attr_set = true;
    }

    init_kernel<<<4096, 256>>>(taus);

    dim3 ggrid(HH / 128, MC / 256, BR);   // (8, 25, 4) = 800 blocks
    for (int c = 0; c < NCHUNK; ++c) {
        const float* Xc = x + (size_t)c * MC * IN_DIM;
        gemm_kernel<<<ggrid, 256>>>(Xc, Wb, bb);
        recur_kernel<<<128, 512, SMEM_RECUR_BYTES>>>(W2, b2, tau1, tau2);
    }
    final_kernel<<<1, 256>>>(out);
}